// round 11
// baseline (speedup 1.0000x reference)
#include <cuda_runtime.h>
#include <math.h>
#include <stdint.h>

// ---------------- problem constants ----------------
#define BSZ    2
#define LEN    2048
#define DIM    768
#define HDIM   1536
#define DSTATE 16
#define ROWS   (BSZ*LEN)   // 4096

#define OUT0_OFF 0
#define OUT1_OFF ((size_t)ROWS*DIM)
#define OUT2_OFF (OUT1_OFF + (size_t)ROWS*HDIM*DSTATE)

// ---------------- scratch ----------------
__device__ float g_apre[ROWS * HDIM];
__device__ float g_g   [ROWS * HDIM];
__device__ float g_a   [ROWS * HDIM];
__device__ float g_aat [ROWS * HDIM];
__device__ float g_agt [ROWS * HDIM];
__device__ float g_dlT [ROWS * HDIM];   // delta, TRANSPOSED [d][b*L+l]
__device__ float g_bmT [ROWS * DSTATE]; // Bm, TRANSPOSED [b][s][l]
__device__ float g_xt  [ROWS * DIM];
__device__ float g_w1t [DIM * HDIM];
__device__ float g_w2t [DIM * HDIM];
__device__ float g_wdt [HDIM * HDIM];
__device__ float g_wft [HDIM * DIM];

// ---------------- PTX helpers ----------------
__device__ __forceinline__ uint32_t smem_u32(const void* p) {
    uint32_t a;
    asm("{ .reg .u64 t; cvta.to.shared.u64 t, %1; cvt.u32.u64 %0, t; }"
        : "=r"(a) : "l"(p));
    return a;
}
#define CP_ASYNC16(dst, src) \
    asm volatile("cp.async.cg.shared.global [%0], [%1], 16;" :: "r"(dst), "l"(src) : "memory")
#define CP_COMMIT()  asm volatile("cp.async.commit_group;" ::: "memory")
#define CP_WAIT2()   asm volatile("cp.async.wait_group 2;" ::: "memory")

__device__ __forceinline__ float rnd_tf32(float f) {
    uint32_t u;
    asm("cvt.rna.tf32.f32 %0, %1;" : "=r"(u) : "f"(f));
    return __uint_as_float(u);
}
__device__ __forceinline__ void mma_tf32(float* c, const uint32_t* a, const uint32_t* b) {
    asm volatile(
        "mma.sync.aligned.m16n8k8.row.col.f32.tf32.tf32.f32 "
        "{%0,%1,%2,%3}, {%4,%5,%6,%7}, {%8,%9}, {%0,%1,%2,%3};"
        : "+f"(c[0]), "+f"(c[1]), "+f"(c[2]), "+f"(c[3])
        : "r"(a[0]), "r"(a[1]), "r"(a[2]), "r"(a[3]), "r"(b[0]), "r"(b[1]));
}

// ---------------- pre-round x + all weights to tf32 ----------------
#define XT4  (ROWS*DIM/4)
#define W14  (DIM*HDIM/4)
#define WD4  (HDIM*HDIM/4)
#define RB0  XT4
#define RB1  (RB0 + W14)
#define RB2  (RB1 + W14)
#define RB3  (RB2 + WD4)
#define RTOT (RB3 + W14)

__global__ void __launch_bounds__(256) round_all_kernel(
    const float4* __restrict__ x,  const float4* __restrict__ w1,
    const float4* __restrict__ w2, const float4* __restrict__ wd,
    const float4* __restrict__ wf,
    float4* __restrict__ xt,  float4* __restrict__ w1t,
    float4* __restrict__ w2t, float4* __restrict__ wdt,
    float4* __restrict__ wft)
{
    int i = blockIdx.x * 256 + threadIdx.x;
    if (i >= RTOT) return;
    const float4* s; float4* d; int off;
    if      (i < RB0) { s = x;  d = xt;  off = i; }
    else if (i < RB1) { s = w1; d = w1t; off = i - RB0; }
    else if (i < RB2) { s = w2; d = w2t; off = i - RB1; }
    else if (i < RB3) { s = wd; d = wdt; off = i - RB2; }
    else              { s = wf; d = wft; off = i - RB3; }
    float4 v = s[off];
    v.x = rnd_tf32(v.x); v.y = rnd_tf32(v.y);
    v.z = rnd_tf32(v.z); v.w = rnd_tf32(v.w);
    d[off] = v;
}

// ---------------- TF32 tensor-core GEMM body (R5 layout) --------------------
// mode 2 stores its output TRANSPOSED: C[col][row] (for the scan's delta).
#define BK 32
#define ASTRIDE 36
#define BSTRIDE 136
#define A_FLOATS (128 * ASTRIDE)                 // 4608
#define STAGE_FLOATS (A_FLOATS + BK * BSTRIDE)   // 8960
#define GEMM_SMEM_BYTES (3 * STAGE_FLOATS * 4)   // 107520

__device__ __forceinline__ void gemm_body(
    const float* __restrict__ A, const float* __restrict__ B,
    const float* __restrict__ bias, const float* __restrict__ bias2,
    float* __restrict__ C, int N, int K, int mode,
    float* smem, int bm, int bn)
{
    const uint32_t smem_b = smem_u32(smem);
    const int tid = threadIdx.x;
    const int wid = tid >> 5, lane = tid & 31;
    const int wm = wid >> 1, wn = wid & 1;      // 2x2 warp grid, 64x64 warp tile
    const int g = lane >> 2, t = lane & 3;

    auto load_tile = [&](int t0, int s) {
        const int k0 = t0 * BK;
        const uint32_t abase = smem_b + (uint32_t)s * (STAGE_FLOATS * 4);
        const uint32_t bbase = abase + A_FLOATS * 4;
        #pragma unroll
        for (int i = 0; i < 8; i++) {
            int idx = i * 128 + tid;
            int r = idx >> 3, c4 = idx & 7;
            CP_ASYNC16(abase + (uint32_t)(r * ASTRIDE + c4 * 4) * 4,
                       A + (size_t)(bm + r) * K + k0 + c4 * 4);
        }
        #pragma unroll
        for (int i = 0; i < 8; i++) {
            int idx = i * 128 + tid;
            int kk = idx >> 5, c4 = idx & 31;
            CP_ASYNC16(bbase + (uint32_t)(kk * BSTRIDE + c4 * 4) * 4,
                       B + (size_t)(k0 + kk) * N + bn + c4 * 4);
        }
    };

    float acc[4][8][4];
    #pragma unroll
    for (int mi = 0; mi < 4; mi++)
        #pragma unroll
        for (int nj = 0; nj < 8; nj++)
            #pragma unroll
            for (int q = 0; q < 4; q++) acc[mi][nj][q] = 0.f;

    const int T = K / BK;
    load_tile(0, 0); CP_COMMIT();
    load_tile(1, 1); CP_COMMIT();

    int s_cur = 0, s_nxt = 2;
    for (int tt = 0; tt < T; tt++) {
        if (tt + 2 < T) load_tile(tt + 2, s_nxt);
        CP_COMMIT();
        CP_WAIT2();
        __syncthreads();

        const float* As = smem + s_cur * STAGE_FLOATS;
        const float* Bs = As + A_FLOATS;

        #pragma unroll
        for (int kk = 0; kk < 4; kk++) {
            uint32_t af[4][4];
            #pragma unroll
            for (int mi = 0; mi < 4; mi++) {
                const float* ap = As + (wm * 64 + mi * 16 + g) * ASTRIDE + kk * 8 + t;
                af[mi][0] = __float_as_uint(ap[0]);
                af[mi][1] = __float_as_uint(ap[8 * ASTRIDE]);
                af[mi][2] = __float_as_uint(ap[4]);
                af[mi][3] = __float_as_uint(ap[8 * ASTRIDE + 4]);
            }
            uint32_t bf[8][2];
            #pragma unroll
            for (int nj = 0; nj < 8; nj++) {
                const float* bp = Bs + (kk * 8 + t) * BSTRIDE + wn * 64 + nj * 8 + g;
                bf[nj][0] = __float_as_uint(bp[0]);
                bf[nj][1] = __float_as_uint(bp[4 * BSTRIDE]);
            }
            #pragma unroll
            for (int mi = 0; mi < 4; mi++)
                #pragma unroll
                for (int nj = 0; nj < 8; nj++)
                    mma_tf32(acc[mi][nj], af[mi], bf[nj]);
        }
        __syncthreads();
        s_cur = (s_cur == 2) ? 0 : s_cur + 1;
        s_nxt = (s_nxt == 2) ? 0 : s_nxt + 1;
    }

    // epilogue
    #pragma unroll
    for (int nj = 0; nj < 8; nj++) {
        const int col = bn + wn * 64 + nj * 8 + t * 2;
        const float bz0 = __ldg(bias + col), bz1 = __ldg(bias + col + 1);
        const float e0 = (mode == 2) ? __ldg(bias2 + col) : 0.f;
        const float e1 = (mode == 2) ? __ldg(bias2 + col + 1) : 0.f;
        #pragma unroll
        for (int mi = 0; mi < 4; mi++) {
            const int row0 = bm + wm * 64 + mi * 16 + g;
            float v[4];
            v[0] = acc[mi][nj][0] + bz0 + e0;
            v[1] = acc[mi][nj][1] + bz1 + e1;
            v[2] = acc[mi][nj][2] + bz0 + e0;
            v[3] = acc[mi][nj][3] + bz1 + e1;
            #pragma unroll
            for (int q = 0; q < 4; q++) {
                if (mode == 1) v[q] = v[q] / (1.f + expf(-v[q]));
                if (mode == 2) v[q] = fmaxf(v[q], 0.f) + log1pf(expf(-fabsf(v[q])));
            }
            if (mode == 2) {
                // transposed store: C[col][row]  (rows consecutive across lanes)
                C[(size_t)col * ROWS + row0]           = v[0];
                C[(size_t)(col + 1) * ROWS + row0]     = v[1];
                C[(size_t)col * ROWS + row0 + 8]       = v[2];
                C[(size_t)(col + 1) * ROWS + row0 + 8] = v[3];
            } else {
                *(float2*)(C + (size_t)row0 * N + col)       = make_float2(v[0], v[1]);
                *(float2*)(C + (size_t)(row0 + 8) * N + col) = make_float2(v[2], v[3]);
            }
        }
    }
}

// ---------------- wb body: BmT = (a @ WB + bB) transposed -------------------
__device__ __forceinline__ void wb_body(
    const float* __restrict__ a, const float* __restrict__ WB,
    const float* __restrict__ bB, float* __restrict__ BmT, int base)
{
    const int tid = threadIdx.x;
    const int w = tid >> 5, lane = tid & 31;
    const int r2 = lane >> 4, s = lane & 15;
    const int row0 = base + w * 4 + r2 * 2;

    const float* ar0 = a + (size_t)row0 * HDIM;
    const float* ar1 = ar0 + HDIM;
    float acc0 = 0.f, acc1 = 0.f;
    #pragma unroll 4
    for (int k = 0; k < HDIM; k += 4) {
        float4 a0 = __ldg((const float4*)(ar0 + k));
        float4 a1 = __ldg((const float4*)(ar1 + k));
        float w0 = __ldg(WB + (size_t)(k + 0) * 16 + s);
        float w1 = __ldg(WB + (size_t)(k + 1) * 16 + s);
        float w2 = __ldg(WB + (size_t)(k + 2) * 16 + s);
        float w3 = __ldg(WB + (size_t)(k + 3) * 16 + s);
        acc0 = fmaf(a0.x, w0, acc0); acc0 = fmaf(a0.y, w1, acc0);
        acc0 = fmaf(a0.z, w2, acc0); acc0 = fmaf(a0.w, w3, acc0);
        acc1 = fmaf(a1.x, w0, acc1); acc1 = fmaf(a1.y, w1, acc1);
        acc1 = fmaf(a1.z, w2, acc1); acc1 = fmaf(a1.w, w3, acc1);
    }
    const float bz = __ldg(bB + s);
    // transposed store: BmT[b][s][l]
    {
        int rb = row0 >> 11, rl = row0 & (LEN - 1);
        BmT[((size_t)rb * DSTATE + s) * LEN + rl] = acc0 + bz;
    }
    {
        int rb = (row0 + 1) >> 11, rl = (row0 + 1) & (LEN - 1);
        BmT[((size_t)rb * DSTATE + s) * LEN + rl] = acc1 + bz;
    }
}

// dual launch: z=0 -> C1; z=1 -> C2 (blocks beyond N2 exit); z=2 -> wb slice
__global__ void __launch_bounds__(128, 2) tc_gemm_dual(
    const float* __restrict__ A1, const float* __restrict__ B1,
    const float* __restrict__ bias1, const float* __restrict__ biasx1,
    float* __restrict__ C1, int N1, int m1,
    const float* __restrict__ A2, const float* __restrict__ B2,
    const float* __restrict__ bias2, const float* __restrict__ biasx2,
    float* __restrict__ C2, int N2, int m2,
    int K,
    const float* __restrict__ wb_a, const float* __restrict__ WB,
    const float* __restrict__ bB, float* __restrict__ BmT)
{
    extern __shared__ float smem[];
    if (blockIdx.z == 0) {
        gemm_body(A1, B1, bias1, biasx1, C1, N1, K, m1, smem,
                  blockIdx.y * 128, blockIdx.x * 128);
    } else if (blockIdx.z == 1) {
        if ((int)blockIdx.x * 128 >= N2) return;
        gemm_body(A2, B2, bias2, biasx2, C2, N2, K, m2, smem,
                  blockIdx.y * 128, blockIdx.x * 128);
    } else {
        if (wb_a == nullptr) return;
        const int bid = blockIdx.y * gridDim.x + blockIdx.x;
        if (bid >= ROWS / 16) return;
        wb_body(wb_a, WB, bB, BmT, bid * 16);
    }
}

// ---------------- conv(K=4)+silu; writes a, tf32(a), tf32(a*g), slice ------
__global__ void __launch_bounds__(256) conv_fuse_kernel(
    const float* __restrict__ apre, const float* __restrict__ cw,
    const float* __restrict__ cb, const float* __restrict__ g,
    float* __restrict__ aa, float* __restrict__ aat,
    float* __restrict__ agt, float* __restrict__ out2)
{
    const int idx = blockIdx.x * 256 + threadIdx.x;
    const int d = idx % HDIM;
    const int r = idx / HDIM;
    const int l = r & (LEN - 1);
    float s = cb[d];
    #pragma unroll
    for (int j = 0; j < 4; j++) {
        const int ll = l - 3 + j;
        if (ll >= 0)
            s = fmaf(apre[(size_t)(r - 3 + j) * HDIM + d], cw[d * 4 + j], s);
    }
    const float a = s / (1.f + expf(-s));
    aa[idx]  = a;
    aat[idx] = rnd_tf32(a);
    agt[idx] = rnd_tf32(a * g[idx]);
    if (d >= 1) out2[(size_t)r * (HDIM - 1) + d - 1] = a;
}

// ---------------- fused selective scan -> hid (vectorized streams) ----------
// 64 threads: 8 channels x 8 s-pairs. delta from dlT (contig l), Bm from BmT
// (contig l), a row-major (broadcast scalar). float2 stores.
__global__ void __launch_bounds__(64) scan_kernel(
    const float* __restrict__ dlT, const float* __restrict__ a,
    const float* __restrict__ BmT, const float* __restrict__ A,
    float* __restrict__ hid)
{
    const int tid = threadIdx.x;
    const int ch = tid >> 3, sp = tid & 7;
    const int g = blockIdx.x * 8 + ch;
    const int b = g / HDIM, d = g % HDIM;
    const int s0 = sp * 2;

    const float Ae0 = expf(-A[d * DSTATE + s0]);
    const float Ae1 = expf(-A[d * DSTATE + s0 + 1]);
    float h0 = 0.f, h1 = 0.f;

    const float* dptr = dlT + (size_t)d * ROWS + (size_t)b * LEN;
    const float* aptr = a   + (size_t)b * LEN * HDIM + d;
    const float* b0p  = BmT + ((size_t)b * DSTATE + s0) * LEN;
    const float* b1p  = b0p + LEN;
    float* hptr = hid + ((size_t)b * LEN * HDIM + d) * DSTATE + s0;

    for (int l0 = 0; l0 < LEN; l0 += 8) {
        const float4 dq0 = *(const float4*)(dptr + l0);
        const float4 dq1 = *(const float4*)(dptr + l0 + 4);
        const float4 p0a = __ldg((const float4*)(b0p + l0));
        const float4 p0b = __ldg((const float4*)(b0p + l0 + 4));
        const float4 p1a = __ldg((const float4*)(b1p + l0));
        const float4 p1b = __ldg((const float4*)(b1p + l0 + 4));
        float av[8];
        #pragma unroll
        for (int u = 0; u < 8; u++)
            av[u] = aptr[(size_t)(l0 + u) * HDIM];

        const float dv[8]  = {dq0.x, dq0.y, dq0.z, dq0.w, dq1.x, dq1.y, dq1.z, dq1.w};
        const float b0v[8] = {p0a.x, p0a.y, p0a.z, p0a.w, p0b.x, p0b.y, p0b.z, p0b.w};
        const float b1v[8] = {p1a.x, p1a.y, p1a.z, p1a.w, p1b.x, p1b.y, p1b.z, p1b.w};

        #pragma unroll
        for (int u = 0; u < 8; u++) {
            const float da = dv[u] * av[u];
            h0 = fmaf(Ae0 * dv[u], h0, b0v[u] * da);
            h1 = fmaf(Ae1 * dv[u], h1, b1v[u] * da);
            __stcs((float2*)(hptr + (size_t)(l0 + u) * (HDIM * DSTATE)),
                   make_float2(h0, h1));
        }
    }
}

// ---------------------------------------------------------------------------
extern "C" void kernel_launch(void* const* d_in, const int* in_sizes, int n_in,
                              void* d_out, int out_size)
{
    const float* x  = (const float*)d_in[0];
    const float* W1 = (const float*)d_in[1];
    const float* b1 = (const float*)d_in[2];
    const float* W2 = (const float*)d_in[3];
    const float* b2 = (const float*)d_in[4];
    const float* cw = (const float*)d_in[5];
    const float* cb = (const float*)d_in[6];
    const float* Wf = (const float*)d_in[7];
    const float* bf = (const float*)d_in[8];
    const float* A  = (const float*)d_in[9];
    const float* WB = (const float*)d_in[10];
    const float* bB = (const float*)d_in[11];
    const float* WD = (const float*)d_in[14];
    const float* bD = (const float*)d_in[15];
    const float* Dv = (const float*)d_in[16];

    float* out = (float*)d_out;

    float *apre, *gg, *aa, *aat, *agt, *dlT, *bmT;
    float *xt, *w1t, *w2t, *wdt, *wft;
    cudaGetSymbolAddress((void**)&apre, g_apre);
    cudaGetSymbolAddress((void**)&gg,   g_g);
    cudaGetSymbolAddress((void**)&aa,   g_a);
    cudaGetSymbolAddress((void**)&aat,  g_aat);
    cudaGetSymbolAddress((void**)&agt,  g_agt);
    cudaGetSymbolAddress((void**)&dlT,  g_dlT);
    cudaGetSymbolAddress((void**)&bmT,  g_bmT);
    cudaGetSymbolAddress((void**)&xt,   g_xt);
    cudaGetSymbolAddress((void**)&w1t,  g_w1t);
    cudaGetSymbolAddress((void**)&w2t,  g_w2t);
    cudaGetSymbolAddress((void**)&wdt,  g_wdt);
    cudaGetSymbolAddress((void**)&wft,  g_wft);

    cudaFuncSetAttribute(tc_gemm_dual, cudaFuncAttributeMaxDynamicSharedMemorySize, GEMM_SMEM_BYTES);

    // 0) pre-round x + weights to tf32
    round_all_kernel<<<(RTOT + 255) / 256, 256>>>(
        (const float4*)x, (const float4*)W1, (const float4*)W2,
        (const float4*)WD, (const float4*)Wf,
        (float4*)xt, (float4*)w1t, (float4*)w2t, (float4*)wdt, (float4*)wft);

    // 1+2) apre = x@W1+b1 (z=0) ; g = silu(x@W2+b2) (z=1); no wb slice
    tc_gemm_dual<<<dim3(HDIM/128, ROWS/128, 2), 128, GEMM_SMEM_BYTES>>>(
        xt, w1t, b1, nullptr, apre, HDIM, 0,
        xt, w2t, b2, nullptr, gg,   HDIM, 1,
        DIM,
        nullptr, nullptr, nullptr, nullptr);

    // 3) conv + silu + a*g + slice
    conv_fuse_kernel<<<(ROWS*HDIM)/256, 256>>>(apre, cw, cb, gg, aa, aat, agt, out + OUT2_OFF);

    // 4+5+6) delta gemm -> dlT (z=0, transposed) ∥ Wf gemm (z=1) ∥ wb -> BmT (z=2)
    tc_gemm_dual<<<dim3(HDIM/128, ROWS/128, 3), 128, GEMM_SMEM_BYTES>>>(
        aat, wdt, bD, Dv,      dlT,             HDIM, 2,
        agt, wft, bf, nullptr, out + OUT0_OFF,  DIM,  0,
        HDIM,
        aa, WB, bB, bmT);

    // 7) hid via vectorized selective scan
    scan_kernel<<<BSZ*HDIM/8, 64>>>(dlT, aa, bmT, A, out + OUT1_OFF);
}

// round 12
// speedup vs baseline: 1.0482x; 1.0482x over previous
#include <cuda_runtime.h>
#include <math.h>
#include <stdint.h>

// ---------------- problem constants ----------------
#define BSZ    2
#define LEN    2048
#define DIM    768
#define HDIM   1536
#define DSTATE 16
#define ROWS   (BSZ*LEN)   // 4096
#define NCH    (BSZ*HDIM)  // 3072 channels
#define QLEN   512         // quarter length
#define NQ     4

#define OUT0_OFF 0
#define OUT1_OFF ((size_t)ROWS*DIM)
#define OUT2_OFF (OUT1_OFF + (size_t)ROWS*HDIM*DSTATE)

// ---------------- scratch ----------------
__device__ float g_apre[ROWS * HDIM];
__device__ float g_g   [ROWS * HDIM];
__device__ float g_a   [ROWS * HDIM];
__device__ float g_aat [ROWS * HDIM];
__device__ float g_agt [ROWS * HDIM];
__device__ float g_dl  [ROWS * HDIM];
__device__ float g_bm  [ROWS * DSTATE];
__device__ float g_xt  [ROWS * DIM];
__device__ float g_w1t [DIM * HDIM];
__device__ float g_w2t [DIM * HDIM];
__device__ float g_wdt [HDIM * HDIM];
__device__ float g_wft [HDIM * DIM];
__device__ float g_P   [3 * NCH * DSTATE];   // segment products, quarters 0..2
__device__ float g_Q   [3 * NCH * DSTATE];   // segment local scans

// ---------------- PTX helpers ----------------
__device__ __forceinline__ uint32_t smem_u32(const void* p) {
    uint32_t a;
    asm("{ .reg .u64 t; cvta.to.shared.u64 t, %1; cvt.u32.u64 %0, t; }"
        : "=r"(a) : "l"(p));
    return a;
}
#define CP_ASYNC16(dst, src) \
    asm volatile("cp.async.cg.shared.global [%0], [%1], 16;" :: "r"(dst), "l"(src) : "memory")
#define CP_COMMIT()  asm volatile("cp.async.commit_group;" ::: "memory")
#define CP_WAIT2()   asm volatile("cp.async.wait_group 2;" ::: "memory")

__device__ __forceinline__ float rnd_tf32(float f) {
    uint32_t u;
    asm("cvt.rna.tf32.f32 %0, %1;" : "=r"(u) : "f"(f));
    return __uint_as_float(u);
}
__device__ __forceinline__ void mma_tf32(float* c, const uint32_t* a, const uint32_t* b) {
    asm volatile(
        "mma.sync.aligned.m16n8k8.row.col.f32.tf32.tf32.f32 "
        "{%0,%1,%2,%3}, {%4,%5,%6,%7}, {%8,%9}, {%0,%1,%2,%3};"
        : "+f"(c[0]), "+f"(c[1]), "+f"(c[2]), "+f"(c[3])
        : "r"(a[0]), "r"(a[1]), "r"(a[2]), "r"(a[3]), "r"(b[0]), "r"(b[1]));
}

// ---------------- pre-round x + all weights to tf32 ----------------
#define XT4  (ROWS*DIM/4)
#define W14  (DIM*HDIM/4)
#define WD4  (HDIM*HDIM/4)
#define RB0  XT4
#define RB1  (RB0 + W14)
#define RB2  (RB1 + W14)
#define RB3  (RB2 + WD4)
#define RTOT (RB3 + W14)

__global__ void __launch_bounds__(256) round_all_kernel(
    const float4* __restrict__ x,  const float4* __restrict__ w1,
    const float4* __restrict__ w2, const float4* __restrict__ wd,
    const float4* __restrict__ wf,
    float4* __restrict__ xt,  float4* __restrict__ w1t,
    float4* __restrict__ w2t, float4* __restrict__ wdt,
    float4* __restrict__ wft)
{
    int i = blockIdx.x * 256 + threadIdx.x;
    if (i >= RTOT) return;
    const float4* s; float4* d; int off;
    if      (i < RB0) { s = x;  d = xt;  off = i; }
    else if (i < RB1) { s = w1; d = w1t; off = i - RB0; }
    else if (i < RB2) { s = w2; d = w2t; off = i - RB1; }
    else if (i < RB3) { s = wd; d = wdt; off = i - RB2; }
    else              { s = wf; d = wft; off = i - RB3; }
    float4 v = s[off];
    v.x = rnd_tf32(v.x); v.y = rnd_tf32(v.y);
    v.z = rnd_tf32(v.z); v.w = rnd_tf32(v.w);
    d[off] = v;
}

// ---------------- TF32 tensor-core GEMM body (R5 layout) --------------------
#define BK 32
#define ASTRIDE 36
#define BSTRIDE 136
#define A_FLOATS (128 * ASTRIDE)                 // 4608
#define STAGE_FLOATS (A_FLOATS + BK * BSTRIDE)   // 8960
#define GEMM_SMEM_BYTES (3 * STAGE_FLOATS * 4)   // 107520

__device__ __forceinline__ void gemm_body(
    const float* __restrict__ A, const float* __restrict__ B,
    const float* __restrict__ bias, const float* __restrict__ bias2,
    float* __restrict__ C, int N, int K, int mode,
    float* smem, int bm, int bn)
{
    const uint32_t smem_b = smem_u32(smem);
    const int tid = threadIdx.x;
    const int wid = tid >> 5, lane = tid & 31;
    const int wm = wid >> 1, wn = wid & 1;      // 2x2 warp grid, 64x64 warp tile
    const int g = lane >> 2, t = lane & 3;

    auto load_tile = [&](int t0, int s) {
        const int k0 = t0 * BK;
        const uint32_t abase = smem_b + (uint32_t)s * (STAGE_FLOATS * 4);
        const uint32_t bbase = abase + A_FLOATS * 4;
        #pragma unroll
        for (int i = 0; i < 8; i++) {
            int idx = i * 128 + tid;
            int r = idx >> 3, c4 = idx & 7;
            CP_ASYNC16(abase + (uint32_t)(r * ASTRIDE + c4 * 4) * 4,
                       A + (size_t)(bm + r) * K + k0 + c4 * 4);
        }
        #pragma unroll
        for (int i = 0; i < 8; i++) {
            int idx = i * 128 + tid;
            int kk = idx >> 5, c4 = idx & 31;
            CP_ASYNC16(bbase + (uint32_t)(kk * BSTRIDE + c4 * 4) * 4,
                       B + (size_t)(k0 + kk) * N + bn + c4 * 4);
        }
    };

    float acc[4][8][4];
    #pragma unroll
    for (int mi = 0; mi < 4; mi++)
        #pragma unroll
        for (int nj = 0; nj < 8; nj++)
            #pragma unroll
            for (int q = 0; q < 4; q++) acc[mi][nj][q] = 0.f;

    const int T = K / BK;
    load_tile(0, 0); CP_COMMIT();
    load_tile(1, 1); CP_COMMIT();

    int s_cur = 0, s_nxt = 2;
    for (int tt = 0; tt < T; tt++) {
        if (tt + 2 < T) load_tile(tt + 2, s_nxt);
        CP_COMMIT();
        CP_WAIT2();
        __syncthreads();

        const float* As = smem + s_cur * STAGE_FLOATS;
        const float* Bs = As + A_FLOATS;

        #pragma unroll
        for (int kk = 0; kk < 4; kk++) {
            uint32_t af[4][4];
            #pragma unroll
            for (int mi = 0; mi < 4; mi++) {
                const float* ap = As + (wm * 64 + mi * 16 + g) * ASTRIDE + kk * 8 + t;
                af[mi][0] = __float_as_uint(ap[0]);
                af[mi][1] = __float_as_uint(ap[8 * ASTRIDE]);
                af[mi][2] = __float_as_uint(ap[4]);
                af[mi][3] = __float_as_uint(ap[8 * ASTRIDE + 4]);
            }
            uint32_t bf[8][2];
            #pragma unroll
            for (int nj = 0; nj < 8; nj++) {
                const float* bp = Bs + (kk * 8 + t) * BSTRIDE + wn * 64 + nj * 8 + g;
                bf[nj][0] = __float_as_uint(bp[0]);
                bf[nj][1] = __float_as_uint(bp[4 * BSTRIDE]);
            }
            #pragma unroll
            for (int mi = 0; mi < 4; mi++)
                #pragma unroll
                for (int nj = 0; nj < 8; nj++)
                    mma_tf32(acc[mi][nj], af[mi], bf[nj]);
        }
        __syncthreads();
        s_cur = (s_cur == 2) ? 0 : s_cur + 1;
        s_nxt = (s_nxt == 2) ? 0 : s_nxt + 1;
    }

    // epilogue
    #pragma unroll
    for (int nj = 0; nj < 8; nj++) {
        const int col = bn + wn * 64 + nj * 8 + t * 2;
        const float bz0 = __ldg(bias + col), bz1 = __ldg(bias + col + 1);
        const float e0 = (mode == 2) ? __ldg(bias2 + col) : 0.f;
        const float e1 = (mode == 2) ? __ldg(bias2 + col + 1) : 0.f;
        #pragma unroll
        for (int mi = 0; mi < 4; mi++) {
            const int row0 = bm + wm * 64 + mi * 16 + g;
            float v[4];
            v[0] = acc[mi][nj][0] + bz0 + e0;
            v[1] = acc[mi][nj][1] + bz1 + e1;
            v[2] = acc[mi][nj][2] + bz0 + e0;
            v[3] = acc[mi][nj][3] + bz1 + e1;
            #pragma unroll
            for (int q = 0; q < 4; q++) {
                if (mode == 1) v[q] = v[q] / (1.f + expf(-v[q]));
                if (mode == 2) v[q] = fmaxf(v[q], 0.f) + log1pf(expf(-fabsf(v[q])));
            }
            *(float2*)(C + (size_t)row0 * N + col)       = make_float2(v[0], v[1]);
            *(float2*)(C + (size_t)(row0 + 8) * N + col) = make_float2(v[2], v[3]);
        }
    }
}

// ---------------- wb body: Bm = a @ WB + bB (row-major) ---------------------
__device__ __forceinline__ void wb_body(
    const float* __restrict__ a, const float* __restrict__ WB,
    const float* __restrict__ bB, float* __restrict__ Bm, int base)
{
    const int tid = threadIdx.x;
    const int w = tid >> 5, lane = tid & 31;
    const int r2 = lane >> 4, s = lane & 15;
    const int row0 = base + w * 4 + r2 * 2;

    const float* ar0 = a + (size_t)row0 * HDIM;
    const float* ar1 = ar0 + HDIM;
    float acc0 = 0.f, acc1 = 0.f;
    #pragma unroll 4
    for (int k = 0; k < HDIM; k += 4) {
        float4 a0 = __ldg((const float4*)(ar0 + k));
        float4 a1 = __ldg((const float4*)(ar1 + k));
        float w0 = __ldg(WB + (size_t)(k + 0) * 16 + s);
        float w1 = __ldg(WB + (size_t)(k + 1) * 16 + s);
        float w2 = __ldg(WB + (size_t)(k + 2) * 16 + s);
        float w3 = __ldg(WB + (size_t)(k + 3) * 16 + s);
        acc0 = fmaf(a0.x, w0, acc0); acc0 = fmaf(a0.y, w1, acc0);
        acc0 = fmaf(a0.z, w2, acc0); acc0 = fmaf(a0.w, w3, acc0);
        acc1 = fmaf(a1.x, w0, acc1); acc1 = fmaf(a1.y, w1, acc1);
        acc1 = fmaf(a1.z, w2, acc1); acc1 = fmaf(a1.w, w3, acc1);
    }
    const float bz = __ldg(bB + s);
    Bm[(row0 + 0) * 16 + s] = acc0 + bz;
    Bm[(row0 + 1) * 16 + s] = acc1 + bz;
}

// dual launch: z=0 -> C1; z=1 -> C2 (blocks beyond N2 exit); z=2 -> wb slice
__global__ void __launch_bounds__(128, 2) tc_gemm_dual(
    const float* __restrict__ A1, const float* __restrict__ B1,
    const float* __restrict__ bias1, const float* __restrict__ biasx1,
    float* __restrict__ C1, int N1, int m1,
    const float* __restrict__ A2, const float* __restrict__ B2,
    const float* __restrict__ bias2, const float* __restrict__ biasx2,
    float* __restrict__ C2, int N2, int m2,
    int K,
    const float* __restrict__ wb_a, const float* __restrict__ WB,
    const float* __restrict__ bB, float* __restrict__ Bm)
{
    extern __shared__ float smem[];
    if (blockIdx.z == 0) {
        gemm_body(A1, B1, bias1, biasx1, C1, N1, K, m1, smem,
                  blockIdx.y * 128, blockIdx.x * 128);
    } else if (blockIdx.z == 1) {
        if ((int)blockIdx.x * 128 >= N2) return;
        gemm_body(A2, B2, bias2, biasx2, C2, N2, K, m2, smem,
                  blockIdx.y * 128, blockIdx.x * 128);
    } else {
        if (wb_a == nullptr) return;
        const int bid = blockIdx.y * gridDim.x + blockIdx.x;
        if (bid >= ROWS / 16) return;
        wb_body(wb_a, WB, bB, Bm, bid * 16);
    }
}

// ---------------- conv(K=4)+silu; writes a, tf32(a), tf32(a*g), slice ------
__global__ void __launch_bounds__(256) conv_fuse_kernel(
    const float* __restrict__ apre, const float* __restrict__ cw,
    const float* __restrict__ cb, const float* __restrict__ g,
    float* __restrict__ aa, float* __restrict__ aat,
    float* __restrict__ agt, float* __restrict__ out2)
{
    const int idx = blockIdx.x * 256 + threadIdx.x;
    const int d = idx % HDIM;
    const int r = idx / HDIM;
    const int l = r & (LEN - 1);
    float s = cb[d];
    #pragma unroll
    for (int j = 0; j < 4; j++) {
        const int ll = l - 3 + j;
        if (ll >= 0)
            s = fmaf(apre[(size_t)(r - 3 + j) * HDIM + d], cw[d * 4 + j], s);
    }
    const float a = s / (1.f + expf(-s));
    aa[idx]  = a;
    aat[idx] = rnd_tf32(a);
    agt[idx] = rnd_tf32(a * g[idx]);
    if (d >= 1) out2[(size_t)r * (HDIM - 1) + d - 1] = a;
}

// ---------------- scan phase 1: per-quarter (P, Q) ---------------------------
// warp = 8 consecutive channels (same b) x 4 s-quads, one quarter (0..2).
// thread: 4 states over 512 timesteps, no hid stores.
__global__ void __launch_bounds__(256) scan_p1(
    const float* __restrict__ dl, const float* __restrict__ a,
    const float* __restrict__ Bm, const float* __restrict__ A,
    float* __restrict__ gP, float* __restrict__ gQ)
{
    const int w = blockIdx.x * 8 + (threadIdx.x >> 5);   // 0..1151
    const int lane = threadIdx.x & 31;
    const int cg = w / 3, qq = w % 3;
    const int ch = lane >> 2, sq = lane & 3;
    const int channel = cg * 8 + ch;                     // 0..3071
    const int b = channel / HDIM, d = channel % HDIM;
    const int s0 = sq * 4;

    float Ae[4];
    #pragma unroll
    for (int i = 0; i < 4; i++) Ae[i] = expf(-__ldg(A + d * DSTATE + s0 + i));

    const int r0 = b * LEN + qq * QLEN;
    const float* dp = dl + (size_t)r0 * HDIM + d;
    const float* ap = a  + (size_t)r0 * HDIM + d;
    const float* bp = Bm + (size_t)r0 * DSTATE + s0;

    float P[4] = {1.f, 1.f, 1.f, 1.f};
    float Q[4] = {0.f, 0.f, 0.f, 0.f};

    #pragma unroll 4
    for (int l = 0; l < QLEN; l++) {
        const float dv = __ldg(dp + (size_t)l * HDIM);
        const float av = __ldg(ap + (size_t)l * HDIM);
        const float4 bv = __ldg((const float4*)(bp + (size_t)l * DSTATE));
        const float da = dv * av;
        const float a0 = Ae[0] * dv, a1 = Ae[1] * dv,
                    a2 = Ae[2] * dv, a3 = Ae[3] * dv;
        P[0] *= a0; P[1] *= a1; P[2] *= a2; P[3] *= a3;
        Q[0] = fmaf(a0, Q[0], bv.x * da);
        Q[1] = fmaf(a1, Q[1], bv.y * da);
        Q[2] = fmaf(a2, Q[2], bv.z * da);
        Q[3] = fmaf(a3, Q[3], bv.w * da);
    }
    const size_t o = ((size_t)qq * NCH + channel) * DSTATE + s0;
    *(float4*)(gP + o) = make_float4(P[0], P[1], P[2], P[3]);
    *(float4*)(gQ + o) = make_float4(Q[0], Q[1], Q[2], Q[3]);
}

// ---------------- scan phase 2: prefix-composed quarter scans -> hid --------
// warp = 8 channels x 4 s-quads, one quarter (0..3). STG.128 stores; per-l a
// full warp writes 512B contiguous.
__global__ void __launch_bounds__(256) scan_p2(
    const float* __restrict__ dl, const float* __restrict__ a,
    const float* __restrict__ Bm, const float* __restrict__ A,
    const float* __restrict__ gP, const float* __restrict__ gQ,
    float* __restrict__ hid)
{
    const int w = blockIdx.x * 8 + (threadIdx.x >> 5);   // 0..1535
    const int lane = threadIdx.x & 31;
    const int cg = w >> 2, qq = w & 3;
    const int ch = lane >> 2, sq = lane & 3;
    const int channel = cg * 8 + ch;
    const int b = channel / HDIM, d = channel % HDIM;
    const int s0 = sq * 4;

    float Ae[4];
    #pragma unroll
    for (int i = 0; i < 4; i++) Ae[i] = expf(-__ldg(A + d * DSTATE + s0 + i));

    // prefix composition over earlier quarters
    float h[4] = {0.f, 0.f, 0.f, 0.f};
    for (int j = 0; j < qq; j++) {
        const size_t o = ((size_t)j * NCH + channel) * DSTATE + s0;
        const float4 Pj = __ldg((const float4*)(gP + o));
        const float4 Qj = __ldg((const float4*)(gQ + o));
        h[0] = fmaf(Pj.x, h[0], Qj.x);
        h[1] = fmaf(Pj.y, h[1], Qj.y);
        h[2] = fmaf(Pj.z, h[2], Qj.z);
        h[3] = fmaf(Pj.w, h[3], Qj.w);
    }

    const int r0 = b * LEN + qq * QLEN;
    const float* dp = dl + (size_t)r0 * HDIM + d;
    const float* ap = a  + (size_t)r0 * HDIM + d;
    const float* bp = Bm + (size_t)r0 * DSTATE + s0;
    float* hp = hid + ((size_t)r0 * HDIM + d) * DSTATE + s0;

    #pragma unroll 4
    for (int l = 0; l < QLEN; l++) {
        const float dv = __ldg(dp + (size_t)l * HDIM);
        const float av = __ldg(ap + (size_t)l * HDIM);
        const float4 bv = __ldg((const float4*)(bp + (size_t)l * DSTATE));
        const float da = dv * av;
        const float a0 = Ae[0] * dv, a1 = Ae[1] * dv,
                    a2 = Ae[2] * dv, a3 = Ae[3] * dv;
        h[0] = fmaf(a0, h[0], bv.x * da);
        h[1] = fmaf(a1, h[1], bv.y * da);
        h[2] = fmaf(a2, h[2], bv.z * da);
        h[3] = fmaf(a3, h[3], bv.w * da);
        __stcs((float4*)(hp + (size_t)l * (HDIM * DSTATE)),
               make_float4(h[0], h[1], h[2], h[3]));
    }
}

// ---------------------------------------------------------------------------
extern "C" void kernel_launch(void* const* d_in, const int* in_sizes, int n_in,
                              void* d_out, int out_size)
{
    const float* x  = (const float*)d_in[0];
    const float* W1 = (const float*)d_in[1];
    const float* b1 = (const float*)d_in[2];
    const float* W2 = (const float*)d_in[3];
    const float* b2 = (const float*)d_in[4];
    const float* cw = (const float*)d_in[5];
    const float* cb = (const float*)d_in[6];
    const float* Wf = (const float*)d_in[7];
    const float* bf = (const float*)d_in[8];
    const float* A  = (const float*)d_in[9];
    const float* WB = (const float*)d_in[10];
    const float* bB = (const float*)d_in[11];
    const float* WD = (const float*)d_in[14];
    const float* bD = (const float*)d_in[15];
    const float* Dv = (const float*)d_in[16];

    float* out = (float*)d_out;

    float *apre, *gg, *aa, *aat, *agt, *dl, *bm, *gP, *gQ;
    float *xt, *w1t, *w2t, *wdt, *wft;
    cudaGetSymbolAddress((void**)&apre, g_apre);
    cudaGetSymbolAddress((void**)&gg,   g_g);
    cudaGetSymbolAddress((void**)&aa,   g_a);
    cudaGetSymbolAddress((void**)&aat,  g_aat);
    cudaGetSymbolAddress((void**)&agt,  g_agt);
    cudaGetSymbolAddress((void**)&dl,   g_dl);
    cudaGetSymbolAddress((void**)&bm,   g_bm);
    cudaGetSymbolAddress((void**)&gP,   g_P);
    cudaGetSymbolAddress((void**)&gQ,   g_Q);
    cudaGetSymbolAddress((void**)&xt,   g_xt);
    cudaGetSymbolAddress((void**)&w1t,  g_w1t);
    cudaGetSymbolAddress((void**)&w2t,  g_w2t);
    cudaGetSymbolAddress((void**)&wdt,  g_wdt);
    cudaGetSymbolAddress((void**)&wft,  g_wft);

    cudaFuncSetAttribute(tc_gemm_dual, cudaFuncAttributeMaxDynamicSharedMemorySize, GEMM_SMEM_BYTES);

    // 0) pre-round x + weights to tf32
    round_all_kernel<<<(RTOT + 255) / 256, 256>>>(
        (const float4*)x, (const float4*)W1, (const float4*)W2,
        (const float4*)WD, (const float4*)Wf,
        (float4*)xt, (float4*)w1t, (float4*)w2t, (float4*)wdt, (float4*)wft);

    // 1+2) apre = x@W1+b1 (z=0) ; g = silu(x@W2+b2) (z=1)
    tc_gemm_dual<<<dim3(HDIM/128, ROWS/128, 2), 128, GEMM_SMEM_BYTES>>>(
        xt, w1t, b1, nullptr, apre, HDIM, 0,
        xt, w2t, b2, nullptr, gg,   HDIM, 1,
        DIM,
        nullptr, nullptr, nullptr, nullptr);

    // 3) conv + silu + a*g + slice
    conv_fuse_kernel<<<(ROWS*HDIM)/256, 256>>>(apre, cw, cb, gg, aa, aat, agt, out + OUT2_OFF);

    // 4+5+6) delta gemm (z=0) ∥ Wf gemm (z=1) ∥ wb (z=2)
    tc_gemm_dual<<<dim3(HDIM/128, ROWS/128, 3), 128, GEMM_SMEM_BYTES>>>(
        aat, wdt, bD, Dv,      dl,              HDIM, 2,
        agt, wft, bf, nullptr, out + OUT0_OFF,  DIM,  0,
        HDIM,
        aa, WB, bB, bm);

    // 7) scan phase 1: quarter (P,Q) for quarters 0..2 (1152 warps)
    scan_p1<<<144, 256>>>(dl, aa, bm, A, gP, gQ);
    // 8) scan phase 2: 4 quarters in parallel (1536 warps), STG.128 hid
    scan_p2<<<192, 256>>>(dl, aa, bm, A, gP, gQ, out + OUT1_OFF);
}

// round 13
// speedup vs baseline: 1.2341x; 1.1774x over previous
#include <cuda_runtime.h>
#include <cuda_fp16.h>
#include <math.h>
#include <stdint.h>

// ---------------- problem constants ----------------
#define BSZ    2
#define LEN    2048
#define DIM    768
#define HDIM   1536
#define DSTATE 16
#define ROWS   (BSZ*LEN)   // 4096

#define OUT0_OFF 0
#define OUT1_OFF ((size_t)ROWS*DIM)
#define OUT2_OFF (OUT1_OFF + (size_t)ROWS*HDIM*DSTATE)

// ---------------- scratch ----------------
__device__ float  g_apre[ROWS * HDIM];
__device__ float  g_g   [ROWS * HDIM];
__device__ float  g_a   [ROWS * HDIM];
__device__ __half g_aat [ROWS * HDIM];    // fp16 a       (WD GEMM A operand)
__device__ __half g_agt [ROWS * HDIM];    // fp16 a*g     (Wf GEMM A operand)
__device__ float  g_dl  [ROWS * HDIM];
__device__ float  g_bm  [ROWS * DSTATE];
__device__ __half g_xt  [ROWS * DIM];     // fp16 x
__device__ __half g_w1t [HDIM * DIM];     // fp16 weights, TRANSPOSED [N][K]
__device__ __half g_w2t [HDIM * DIM];
__device__ __half g_wdt [HDIM * HDIM];
__device__ __half g_wft [DIM * HDIM];

// ---------------- PTX helpers ----------------
__device__ __forceinline__ uint32_t smem_u32(const void* p) {
    uint32_t a;
    asm("{ .reg .u64 t; cvta.to.shared.u64 t, %1; cvt.u32.u64 %0, t; }"
        : "=r"(a) : "l"(p));
    return a;
}
#define CP_ASYNC16(dst, src) \
    asm volatile("cp.async.cg.shared.global [%0], [%1], 16;" :: "r"(dst), "l"(src) : "memory")
#define CP_COMMIT()  asm volatile("cp.async.commit_group;" ::: "memory")
#define CP_WAIT2()   asm volatile("cp.async.wait_group 2;" ::: "memory")

__device__ __forceinline__ void mma_f16(float* c, const uint32_t* a, const uint32_t* b) {
    asm volatile(
        "mma.sync.aligned.m16n8k16.row.col.f32.f16.f16.f32 "
        "{%0,%1,%2,%3}, {%4,%5,%6,%7}, {%8,%9}, {%0,%1,%2,%3};"
        : "+f"(c[0]), "+f"(c[1]), "+f"(c[2]), "+f"(c[3])
        : "r"(a[0]), "r"(a[1]), "r"(a[2]), "r"(a[3]), "r"(b[0]), "r"(b[1]));
}

// ---------------- x -> fp16 ----------------
__global__ void __launch_bounds__(256) convert_x_kernel(
    const float4* __restrict__ x, __half2* __restrict__ xt)
{
    const int i = blockIdx.x * 256 + threadIdx.x;   // ROWS*DIM/4 exact
    float4 v = x[i];
    xt[2 * i]     = __floats2half2_rn(v.x, v.y);
    xt[2 * i + 1] = __floats2half2_rn(v.z, v.w);
}

// ---------------- weights: transpose [K][N] -> [N][K] + fp16 ----------------
__global__ void __launch_bounds__(256) transpose_w_kernel(
    const float* __restrict__ w1, const float* __restrict__ w2,
    const float* __restrict__ wd, const float* __restrict__ wf,
    __half* __restrict__ o1, __half* __restrict__ o2,
    __half* __restrict__ od, __half* __restrict__ of)
{
    __shared__ float tile[32][33];
    const int z = blockIdx.z;
    const float* src; __half* dst; int K, N;
    if      (z == 0) { src = w1; dst = o1; K = DIM;  N = HDIM; }
    else if (z == 1) { src = w2; dst = o2; K = DIM;  N = HDIM; }
    else if (z == 2) { src = wd; dst = od; K = HDIM; N = HDIM; }
    else             { src = wf; dst = of; K = HDIM; N = DIM;  }
    const int kb = blockIdx.y * 32, nb = blockIdx.x * 32;
    if (kb >= K || nb >= N) return;
    const int tx = threadIdx.x & 31, ty = threadIdx.x >> 5;
    #pragma unroll
    for (int i = 0; i < 4; i++)
        tile[ty + 8 * i][tx] = src[(size_t)(kb + ty + 8 * i) * N + nb + tx];
    __syncthreads();
    #pragma unroll
    for (int i = 0; i < 4; i++)
        dst[(size_t)(nb + ty + 8 * i) * K + kb + tx] =
            __float2half_rn(tile[tx][ty + 8 * i]);
}

// ---------------- fp16 tensor-core GEMM body --------------------------------
// A [M][K] fp16 row-major, B [N][K] fp16 (pre-transposed). 128x128 CTA tile,
// 4 warps 64x64 each, 3-stage cp.async, m16n8k16, fp32 accum.
// smem per stage: A 128x40 halfs (10240B) + B 128x40 halfs = 20480B.
#define BKH 32                                    // K elems per tile
#define HSTRIDE 40                                // halfs per smem row
#define STAGE_BYTES (2 * 128 * HSTRIDE * 2)       // 20480
#define GEMM_SMEM_BYTES (3 * STAGE_BYTES)         // 61440

__device__ __forceinline__ void gemm_body(
    const __half* __restrict__ A, const __half* __restrict__ B,
    const float* __restrict__ bias, const float* __restrict__ bias2,
    float* __restrict__ C, int N, int K, int mode,
    char* smem, int bm, int bn)
{
    const uint32_t smem_b = smem_u32(smem);
    const int tid = threadIdx.x;
    const int wid = tid >> 5, lane = tid & 31;
    const int wm = wid >> 1, wn = wid & 1;        // 2x2 warps, 64x64 tiles
    const int g = lane >> 2, t = lane & 3;

    auto load_tile = [&](int t0, int s) {
        const int k0 = t0 * BKH;
        const uint32_t abase = smem_b + (uint32_t)s * STAGE_BYTES;
        const uint32_t bbase = abase + 128 * HSTRIDE * 2;
        #pragma unroll
        for (int i = 0; i < 4; i++) {             // A: 128 rows x 32 halfs
            int idx = i * 128 + tid;
            int r = idx >> 2, c8 = idx & 3;
            CP_ASYNC16(abase + (uint32_t)(r * (HSTRIDE * 2) + c8 * 16),
                       A + (size_t)(bm + r) * K + k0 + c8 * 8);
        }
        #pragma unroll
        for (int i = 0; i < 4; i++) {             // B: 128 n-rows x 32 halfs
            int idx = i * 128 + tid;
            int n = idx >> 2, c8 = idx & 3;
            CP_ASYNC16(bbase + (uint32_t)(n * (HSTRIDE * 2) + c8 * 16),
                       B + (size_t)(bn + n) * K + k0 + c8 * 8);
        }
    };

    float acc[4][8][4];
    #pragma unroll
    for (int mi = 0; mi < 4; mi++)
        #pragma unroll
        for (int nj = 0; nj < 8; nj++)
            #pragma unroll
            for (int q = 0; q < 4; q++) acc[mi][nj][q] = 0.f;

    const int T = K / BKH;
    load_tile(0, 0); CP_COMMIT();
    load_tile(1, 1); CP_COMMIT();

    int s_cur = 0, s_nxt = 2;
    for (int tt = 0; tt < T; tt++) {
        if (tt + 2 < T) load_tile(tt + 2, s_nxt);
        CP_COMMIT();
        CP_WAIT2();
        __syncthreads();

        const uint32_t* Sw = (const uint32_t*)(smem + s_cur * STAGE_BYTES);
        const uint32_t* Aw = Sw;                        // words (half2)
        const uint32_t* Bw = Sw + 128 * (HSTRIDE / 2);  // +2560 words

        #pragma unroll
        for (int kk = 0; kk < 2; kk++) {                // K=16 per step
            uint32_t af[4][4];
            #pragma unroll
            for (int mi = 0; mi < 4; mi++) {
                const int row = wm * 64 + mi * 16 + g;
                const uint32_t* ap = Aw + row * (HSTRIDE / 2) + kk * 8 + t;
                af[mi][0] = ap[0];                       // (g,      2t)
                af[mi][1] = ap[8 * (HSTRIDE / 2)];       // (g+8,    2t)
                af[mi][2] = ap[4];                       // (g,    2t+8)
                af[mi][3] = ap[8 * (HSTRIDE / 2) + 4];   // (g+8,  2t+8)
            }
            uint32_t bf[8][2];
            #pragma unroll
            for (int nj = 0; nj < 8; nj++) {
                const int n = wn * 64 + nj * 8 + g;
                const uint32_t* bp = Bw + n * (HSTRIDE / 2) + kk * 8 + t;
                bf[nj][0] = bp[0];                       // (2t,   n)
                bf[nj][1] = bp[4];                       // (2t+8, n)
            }
            #pragma unroll
            for (int mi = 0; mi < 4; mi++)
                #pragma unroll
                for (int nj = 0; nj < 8; nj++)
                    mma_f16(acc[mi][nj], af[mi], bf[nj]);
        }
        __syncthreads();
        s_cur = (s_cur == 2) ? 0 : s_cur + 1;
        s_nxt = (s_nxt == 2) ? 0 : s_nxt + 1;
    }

    // epilogue (C fragment layout identical to tf32 version)
    #pragma unroll
    for (int nj = 0; nj < 8; nj++) {
        const int col = bn + wn * 64 + nj * 8 + t * 2;
        const float bz0 = __ldg(bias + col), bz1 = __ldg(bias + col + 1);
        const float e0 = (mode == 2) ? __ldg(bias2 + col) : 0.f;
        const float e1 = (mode == 2) ? __ldg(bias2 + col + 1) : 0.f;
        #pragma unroll
        for (int mi = 0; mi < 4; mi++) {
            const int row0 = bm + wm * 64 + mi * 16 + g;
            float v[4];
            v[0] = acc[mi][nj][0] + bz0 + e0;
            v[1] = acc[mi][nj][1] + bz1 + e1;
            v[2] = acc[mi][nj][2] + bz0 + e0;
            v[3] = acc[mi][nj][3] + bz1 + e1;
            #pragma unroll
            for (int q = 0; q < 4; q++) {
                if (mode == 1) v[q] = v[q] / (1.f + expf(-v[q]));
                if (mode == 2) v[q] = fmaxf(v[q], 0.f) + log1pf(expf(-fabsf(v[q])));
            }
            *(float2*)(C + (size_t)row0 * N + col)       = make_float2(v[0], v[1]);
            *(float2*)(C + (size_t)(row0 + 8) * N + col) = make_float2(v[2], v[3]);
        }
    }
}

// ---------------- wb body: Bm = a @ WB + bB (fp32) ---------------------------
__device__ __forceinline__ void wb_body(
    const float* __restrict__ a, const float* __restrict__ WB,
    const float* __restrict__ bB, float* __restrict__ Bm, int base)
{
    const int tid = threadIdx.x;
    const int w = tid >> 5, lane = tid & 31;
    const int r2 = lane >> 4, s = lane & 15;
    const int row0 = base + w * 4 + r2 * 2;

    const float* ar0 = a + (size_t)row0 * HDIM;
    const float* ar1 = ar0 + HDIM;
    float acc0 = 0.f, acc1 = 0.f;
    #pragma unroll 4
    for (int k = 0; k < HDIM; k += 4) {
        float4 a0 = __ldg((const float4*)(ar0 + k));
        float4 a1 = __ldg((const float4*)(ar1 + k));
        float w0 = __ldg(WB + (size_t)(k + 0) * 16 + s);
        float w1 = __ldg(WB + (size_t)(k + 1) * 16 + s);
        float w2 = __ldg(WB + (size_t)(k + 2) * 16 + s);
        float w3 = __ldg(WB + (size_t)(k + 3) * 16 + s);
        acc0 = fmaf(a0.x, w0, acc0); acc0 = fmaf(a0.y, w1, acc0);
        acc0 = fmaf(a0.z, w2, acc0); acc0 = fmaf(a0.w, w3, acc0);
        acc1 = fmaf(a1.x, w0, acc1); acc1 = fmaf(a1.y, w1, acc1);
        acc1 = fmaf(a1.z, w2, acc1); acc1 = fmaf(a1.w, w3, acc1);
    }
    const float bz = __ldg(bB + s);
    Bm[(row0 + 0) * 16 + s] = acc0 + bz;
    Bm[(row0 + 1) * 16 + s] = acc1 + bz;
}

// dual launch: z=0 -> C1; z=1 -> C2 (extra blocks exit); z=2 -> wb slice
__global__ void __launch_bounds__(128, 2) tc_gemm_dual(
    const __half* __restrict__ A1, const __half* __restrict__ B1,
    const float* __restrict__ bias1, const float* __restrict__ biasx1,
    float* __restrict__ C1, int N1, int m1,
    const __half* __restrict__ A2, const __half* __restrict__ B2,
    const float* __restrict__ bias2, const float* __restrict__ biasx2,
    float* __restrict__ C2, int N2, int m2,
    int K,
    const float* __restrict__ wb_a, const float* __restrict__ WB,
    const float* __restrict__ bB, float* __restrict__ Bm)
{
    extern __shared__ char smem[];
    if (blockIdx.z == 0) {
        gemm_body(A1, B1, bias1, biasx1, C1, N1, K, m1, smem,
                  blockIdx.y * 128, blockIdx.x * 128);
    } else if (blockIdx.z == 1) {
        if ((int)blockIdx.x * 128 >= N2) return;
        gemm_body(A2, B2, bias2, biasx2, C2, N2, K, m2, smem,
                  blockIdx.y * 128, blockIdx.x * 128);
    } else {
        if (wb_a == nullptr) return;
        const int bid = blockIdx.y * gridDim.x + blockIdx.x;
        if (bid >= ROWS / 16) return;
        wb_body(wb_a, WB, bB, Bm, bid * 16);
    }
}

// ---------------- conv(K=4)+silu; writes a (f32), fp16 a, fp16 a*g, slice ---
__global__ void __launch_bounds__(256) conv_fuse_kernel(
    const float* __restrict__ apre, const float* __restrict__ cw,
    const float* __restrict__ cb, const float* __restrict__ g,
    float* __restrict__ aa, __half* __restrict__ aat,
    __half* __restrict__ agt, float* __restrict__ out2)
{
    const int idx = blockIdx.x * 256 + threadIdx.x;
    const int d = idx % HDIM;
    const int r = idx / HDIM;
    const int l = r & (LEN - 1);
    float s = cb[d];
    #pragma unroll
    for (int j = 0; j < 4; j++) {
        const int ll = l - 3 + j;
        if (ll >= 0)
            s = fmaf(apre[(size_t)(r - 3 + j) * HDIM + d], cw[d * 4 + j], s);
    }
    const float a = s / (1.f + expf(-s));
    aa[idx]  = a;
    aat[idx] = __float2half_rn(a);
    agt[idx] = __float2half_rn(a * g[idx]);
    if (d >= 1) out2[(size_t)r * (HDIM - 1) + d - 1] = a;
}

// ---------------- fused selective scan -> hid (R10 version) -----------------
__global__ void __launch_bounds__(256) scan_kernel(
    const float* __restrict__ delta, const float* __restrict__ a,
    const float* __restrict__ Bm, const float* __restrict__ A,
    float* __restrict__ hid)
{
    const int g = blockIdx.x * 16 + (threadIdx.x >> 4);
    const int s = threadIdx.x & 15;
    const int b = g / HDIM;
    const int d = g % HDIM;

    const float Ae = expf(-A[d * DSTATE + s]);
    float h = 0.f;

    const float* dptr = delta + (size_t)b * LEN * HDIM + d;
    const float* aptr = a     + (size_t)b * LEN * HDIM + d;
    const float* bptr = Bm    + (size_t)b * LEN * DSTATE + s;
    float* hptr = hid + ((size_t)b * LEN * HDIM + d) * DSTATE + s;

    for (int l0 = 0; l0 < LEN; l0 += 8) {
        float dv[8], av[8], bv[8];
        #pragma unroll
        for (int u = 0; u < 8; u++) {
            dv[u] = dptr[(size_t)(l0 + u) * HDIM];
            av[u] = aptr[(size_t)(l0 + u) * HDIM];
            bv[u] = bptr[(size_t)(l0 + u) * DSTATE];
        }
        #pragma unroll
        for (int u = 0; u < 8; u++) {
            h = fmaf(Ae * dv[u], h, bv[u] * dv[u] * av[u]);
            __stcs(hptr + (size_t)(l0 + u) * (HDIM * DSTATE), h);
        }
    }
}

// ---------------------------------------------------------------------------
extern "C" void kernel_launch(void* const* d_in, const int* in_sizes, int n_in,
                              void* d_out, int out_size)
{
    const float* x  = (const float*)d_in[0];
    const float* W1 = (const float*)d_in[1];
    const float* b1 = (const float*)d_in[2];
    const float* W2 = (const float*)d_in[3];
    const float* b2 = (const float*)d_in[4];
    const float* cw = (const float*)d_in[5];
    const float* cb = (const float*)d_in[6];
    const float* Wf = (const float*)d_in[7];
    const float* bf = (const float*)d_in[8];
    const float* A  = (const float*)d_in[9];
    const float* WB = (const float*)d_in[10];
    const float* bB = (const float*)d_in[11];
    const float* WD = (const float*)d_in[14];
    const float* bD = (const float*)d_in[15];
    const float* Dv = (const float*)d_in[16];

    float* out = (float*)d_out;

    float *apre, *gg, *aa, *dl, *bm;
    __half *aat, *agt, *xt, *w1t, *w2t, *wdt, *wft;
    cudaGetSymbolAddress((void**)&apre, g_apre);
    cudaGetSymbolAddress((void**)&gg,   g_g);
    cudaGetSymbolAddress((void**)&aa,   g_a);
    cudaGetSymbolAddress((void**)&aat,  g_aat);
    cudaGetSymbolAddress((void**)&agt,  g_agt);
    cudaGetSymbolAddress((void**)&dl,   g_dl);
    cudaGetSymbolAddress((void**)&bm,   g_bm);
    cudaGetSymbolAddress((void**)&xt,   g_xt);
    cudaGetSymbolAddress((void**)&w1t,  g_w1t);
    cudaGetSymbolAddress((void**)&w2t,  g_w2t);
    cudaGetSymbolAddress((void**)&wdt,  g_wdt);
    cudaGetSymbolAddress((void**)&wft,  g_wft);

    cudaFuncSetAttribute(tc_gemm_dual, cudaFuncAttributeMaxDynamicSharedMemorySize, GEMM_SMEM_BYTES);

    // 0) x -> fp16; weights -> fp16 transposed [N][K]
    convert_x_kernel<<<(ROWS*DIM/4)/256, 256>>>((const float4*)x, (__half2*)xt);
    transpose_w_kernel<<<dim3(HDIM/32, HDIM/32, 4), 256>>>(
        W1, W2, WD, Wf, w1t, w2t, wdt, wft);

    // 1+2) apre = x@W1+b1 (z=0) ; g = silu(x@W2+b2) (z=1)
    tc_gemm_dual<<<dim3(HDIM/128, ROWS/128, 2), 128, GEMM_SMEM_BYTES>>>(
        xt, w1t, b1, nullptr, apre, HDIM, 0,
        xt, w2t, b2, nullptr, gg,   HDIM, 1,
        DIM,
        nullptr, nullptr, nullptr, nullptr);

    // 3) conv + silu + a*g + slice
    conv_fuse_kernel<<<(ROWS*HDIM)/256, 256>>>(apre, cw, cb, gg, aa, aat, agt, out + OUT2_OFF);

    // 4+5+6) delta gemm (z=0) ∥ Wf gemm (z=1) ∥ wb (z=2)
    tc_gemm_dual<<<dim3(HDIM/128, ROWS/128, 3), 128, GEMM_SMEM_BYTES>>>(
        aat, wdt, bD, Dv,      dl,              HDIM, 2,
        agt, wft, bf, nullptr, out + OUT0_OFF,  DIM,  0,
        HDIM,
        aa, WB, bB, bm);

    // 7) hid via fused selective scan
    scan_kernel<<<(BSZ*HDIM)/16, 256>>>(dl, aa, bm, A, out + OUT1_OFF);
}